// round 3
// baseline (speedup 1.0000x reference)
#include <cuda_runtime.h>

#define NRAYS    16384
#define NSAMPLES 1024
#define EPS      0.05f
#define WARPS_PER_BLOCK 8
#define THREADS  (WARPS_PER_BLOCK * 32)

// ---------------- scratch (no allocation allowed) ----------------
__device__ double g_empty_acc;
__device__ double g_near_acc;
__device__ double g_nmask_acc;
__device__ int    g_mask_kind;   // 0 = u8/bool, 1 = int32, 2 = float32

// ---------------- init: zero accumulators + detect mask dtype ----------------
// Scans the first NRAYS bytes of the mask buffer (in-bounds for u8, i32 and
// f32 layouts). Classifies by which byte offsets (mod 4) ever hold nonzero:
//   u8 bool  : nonzeros at all offsets (in particular offset 1)
//   int32 0/1: nonzeros only at offset 0
//   f32 0/1  : 1.0f = 00 00 80 3F -> nonzeros at offsets 2 and 3 only
__global__ void init_detect_kernel(const unsigned char* __restrict__ mask_bytes) {
    __shared__ int flags;
    if (threadIdx.x == 0) flags = 0;
    __syncthreads();
    int local = 0;
    for (int i = threadIdx.x; i < NRAYS; i += blockDim.x) {
        if (mask_bytes[i]) local |= 1 << (i & 3);
    }
    if (local) atomicOr(&flags, local);
    __syncthreads();
    if (threadIdx.x == 0) {
        int f = flags;
        int kind;
        if      (f & 0x2) kind = 0;   // offset-1 nonzero -> bool/u8
        else if (f & 0xC) kind = 2;   // offsets 2/3 -> float32
        else if (f & 0x1) kind = 1;   // only offset 0 -> int32
        else              kind = 0;   // degenerate (all-false mask)
        g_mask_kind = kind;
        g_empty_acc = 0.0;
        g_near_acc  = 0.0;
        g_nmask_acc = 0.0;
    }
}

// ---------------- main: one warp per ray, streaming pass ----------------
__global__ __launch_bounds__(THREADS) void loss_kernel(
    const float* __restrict__ ray_depth,
    const float* __restrict__ z_vals,
    const float* __restrict__ weights,
    const void*  __restrict__ mask)
{
    const int warp = threadIdx.x >> 5;
    const int lane = threadIdx.x & 31;
    const int ray  = blockIdx.x * WARPS_PER_BLOCK + warp;   // grid sized exactly

    // per-ray mask as 0/1 float, per detected dtype
    float m;
    {
        const int kind = g_mask_kind;
        if (kind == 0)      m = ((const unsigned char*)mask)[ray] ? 1.0f : 0.0f;
        else if (kind == 1) m = ((const int*)mask)[ray]           ? 1.0f : 0.0f;
        else                m = (((const float*)mask)[ray] != 0.0f) ? 1.0f : 0.0f;
    }

    const float d  = __ldg(&ray_depth[ray]);
    const float lo = d - EPS;
    const float hi = d + EPS;

    const float4* __restrict__ zp =
        (const float4*)(z_vals  + (size_t)ray * NSAMPLES);
    const float4* __restrict__ wp =
        (const float4*)(weights + (size_t)ray * NSAMPLES);

    float empty  = 0.0f;   // sum of w^2 where z <  lo
    float near_s = 0.0f;   // sum of w   where lo <= z < hi

    #pragma unroll
    for (int k = 0; k < NSAMPLES / (32 * 4); k++) {          // 8 iterations
        const float4 z = __ldg(&zp[k * 32 + lane]);          // 512B/warp, coalesced
        const float4 w = __ldg(&wp[k * 32 + lane]);

        if (z.x < lo) empty = fmaf(w.x, w.x, empty); else if (z.x < hi) near_s += w.x;
        if (z.y < lo) empty = fmaf(w.y, w.y, empty); else if (z.y < hi) near_s += w.y;
        if (z.z < lo) empty = fmaf(w.z, w.z, empty); else if (z.z < hi) near_s += w.z;
        if (z.w < lo) empty = fmaf(w.w, w.w, empty); else if (z.w < hi) near_s += w.w;
    }

    // warp tree-reduce both sums
    #pragma unroll
    for (int off = 16; off > 0; off >>= 1) {
        empty  += __shfl_xor_sync(0xFFFFFFFFu, empty,  off);
        near_s += __shfl_xor_sync(0xFFFFFFFFu, near_s, off);
    }

    // block reduce across 8 warps, then 3 atomics per block (2048 total)
    __shared__ float s_e[WARPS_PER_BLOCK], s_n[WARPS_PER_BLOCK], s_m[WARPS_PER_BLOCK];
    if (lane == 0) {
        const float dn = 1.0f - near_s;
        s_e[warp] = empty * m;
        s_n[warp] = dn * dn * m;
        s_m[warp] = m;
    }
    __syncthreads();
    if (threadIdx.x == 0) {
        float E = 0.0f, N = 0.0f, M = 0.0f;
        #pragma unroll
        for (int i = 0; i < WARPS_PER_BLOCK; i++) { E += s_e[i]; N += s_n[i]; M += s_m[i]; }
        atomicAdd(&g_empty_acc, (double)E);
        atomicAdd(&g_near_acc,  (double)N);
        atomicAdd(&g_nmask_acc, (double)M);
    }
}

// ---------------- finalize ----------------
__global__ void finalize_kernel(float* __restrict__ out) {
    const double nm = g_nmask_acc;
    out[0] = (float)(g_empty_acc / nm);   // loss_empty
    out[1] = (float)(g_near_acc  / nm);   // loss_near
}

// ---------------- launch ----------------
extern "C" void kernel_launch(void* const* d_in, const int* in_sizes, int n_in,
                              void* d_out, int out_size) {
    const float* ray_depth = (const float*)d_in[0];   // [16384, 1]
    const float* z_vals    = (const float*)d_in[1];   // [16384, 1024] sorted
    const float* weights   = (const float*)d_in[2];   // [16384, 1024]
    const void*  ray_mask  = d_in[3];                 // [16384] bool/i32/f32

    init_detect_kernel<<<1, 256>>>((const unsigned char*)ray_mask);
    loss_kernel<<<NRAYS / WARPS_PER_BLOCK, THREADS>>>(ray_depth, z_vals, weights, ray_mask);
    finalize_kernel<<<1, 1>>>((float*)d_out);
}

// round 4
// speedup vs baseline: 1.1985x; 1.1985x over previous
#include <cuda_runtime.h>

#define NRAYS    16384
#define NSAMPLES 1024
#define EPS      0.05f
#define WARPS_PER_BLOCK 8
#define THREADS  (WARPS_PER_BLOCK * 32)
#define GRID     (NRAYS / WARPS_PER_BLOCK)

// ---------------- scratch (no allocation allowed) ----------------
__device__ double       g_empty_acc;
__device__ double       g_near_acc;
__device__ double       g_nmask_acc;
__device__ int          g_mask_kind;   // 0 = u8/bool, 1 = int32, 2 = float32
__device__ unsigned int g_done;        // block-completion ticket

// ---------------- init: zero accumulators + detect mask dtype ----------------
// Scans the first NRAYS bytes of the mask buffer (in-bounds for u8, i32 and
// f32 layouts) with uint4 loads. Classifies by which byte offsets (mod 4)
// ever hold nonzero:
//   u8 bool  : nonzeros at offset 1 (and others)
//   int32 0/1: nonzeros only at offset 0
//   f32 0/1  : 1.0f = 00 00 80 3F -> nonzeros at offsets 2/3 only
__global__ void init_detect_kernel(const uint4* __restrict__ mask_vec) {
    __shared__ int s_flags[8];
    const int tid  = threadIdx.x;
    const int warp = tid >> 5;

    int local = 0;
    // 16384 bytes = 1024 uint4; 256 threads -> 4 independent loads each
    #pragma unroll
    for (int k = 0; k < 4; k++) {
        const uint4 v = mask_vec[k * 256 + tid];
        const unsigned int w0 = v.x | v.y | v.z | v.w;  // OR of 4 words keeps byte lanes
        if (w0 & 0x000000FFu) local |= 0x1;             // offset 0
        if (w0 & 0x0000FF00u) local |= 0x2;             // offset 1
        if (w0 & 0xFFFF0000u) local |= 0xC;             // offsets 2/3
    }
    local = __reduce_or_sync(0xFFFFFFFFu, local);
    if ((tid & 31) == 0) s_flags[warp] = local;
    __syncthreads();

    if (tid == 0) {
        int f = 0;
        #pragma unroll
        for (int i = 0; i < 8; i++) f |= s_flags[i];
        int kind;
        if      (f & 0x2) kind = 0;   // byte offset 1 nonzero -> bool/u8
        else if (f & 0xC) kind = 2;   // offsets 2/3 -> float32
        else if (f & 0x1) kind = 1;   // only offset 0 -> int32
        else              kind = 0;   // degenerate (all-false mask)
        g_mask_kind = kind;
        g_empty_acc = 0.0;
        g_near_acc  = 0.0;
        g_nmask_acc = 0.0;
        g_done      = 0u;
    }
}

// ---------------- main: one warp per ray, streaming pass + self-finalize ----
__global__ __launch_bounds__(THREADS) void loss_kernel(
    const float* __restrict__ ray_depth,
    const float* __restrict__ z_vals,
    const float* __restrict__ weights,
    const void*  __restrict__ mask,
    float*       __restrict__ out)
{
    const int warp = threadIdx.x >> 5;
    const int lane = threadIdx.x & 31;
    const int ray  = blockIdx.x * WARPS_PER_BLOCK + warp;   // grid sized exactly

    // per-ray mask as 0/1 float, per detected dtype
    float m;
    {
        const int kind = g_mask_kind;
        if (kind == 0)      m = ((const unsigned char*)mask)[ray] ? 1.0f : 0.0f;
        else if (kind == 1) m = ((const int*)mask)[ray]           ? 1.0f : 0.0f;
        else                m = (((const float*)mask)[ray] != 0.0f) ? 1.0f : 0.0f;
    }

    const float d  = __ldg(&ray_depth[ray]);
    const float lo = d - EPS;
    const float hi = d + EPS;

    const float4* __restrict__ zp =
        (const float4*)(z_vals  + (size_t)ray * NSAMPLES);
    const float4* __restrict__ wp =
        (const float4*)(weights + (size_t)ray * NSAMPLES);

    float empty  = 0.0f;   // sum of w^2 where z <  lo
    float near_s = 0.0f;   // sum of w   where lo <= z < hi

    #pragma unroll
    for (int k = 0; k < NSAMPLES / (32 * 4); k++) {          // 8 iterations
        const float4 z = __ldcs(&zp[k * 32 + lane]);         // evict-first: read-once data
        const float4 w = __ldcs(&wp[k * 32 + lane]);

        if (z.x < lo) empty = fmaf(w.x, w.x, empty); else if (z.x < hi) near_s += w.x;
        if (z.y < lo) empty = fmaf(w.y, w.y, empty); else if (z.y < hi) near_s += w.y;
        if (z.z < lo) empty = fmaf(w.z, w.z, empty); else if (z.z < hi) near_s += w.z;
        if (z.w < lo) empty = fmaf(w.w, w.w, empty); else if (z.w < hi) near_s += w.w;
    }

    // warp tree-reduce both sums
    #pragma unroll
    for (int off = 16; off > 0; off >>= 1) {
        empty  += __shfl_xor_sync(0xFFFFFFFFu, empty,  off);
        near_s += __shfl_xor_sync(0xFFFFFFFFu, near_s, off);
    }

    // block reduce across 8 warps, then 3 atomics per block
    __shared__ float s_e[WARPS_PER_BLOCK], s_n[WARPS_PER_BLOCK], s_m[WARPS_PER_BLOCK];
    if (lane == 0) {
        const float dn = 1.0f - near_s;
        s_e[warp] = empty * m;
        s_n[warp] = dn * dn * m;
        s_m[warp] = m;
    }
    __syncthreads();
    if (threadIdx.x == 0) {
        float E = 0.0f, N = 0.0f, M = 0.0f;
        #pragma unroll
        for (int i = 0; i < WARPS_PER_BLOCK; i++) { E += s_e[i]; N += s_n[i]; M += s_m[i]; }
        atomicAdd(&g_empty_acc, (double)E);
        atomicAdd(&g_near_acc,  (double)N);
        atomicAdd(&g_nmask_acc, (double)M);

        // last block to finish finalizes the output (no separate kernel)
        __threadfence();
        const unsigned int ticket = atomicAdd(&g_done, 1u);
        if (ticket == (unsigned int)(GRID - 1)) {
            const double nm = g_nmask_acc;
            out[0] = (float)(g_empty_acc / nm);   // loss_empty
            out[1] = (float)(g_near_acc  / nm);   // loss_near
        }
    }
}

// ---------------- launch ----------------
extern "C" void kernel_launch(void* const* d_in, const int* in_sizes, int n_in,
                              void* d_out, int out_size) {
    const float* ray_depth = (const float*)d_in[0];   // [16384, 1]
    const float* z_vals    = (const float*)d_in[1];   // [16384, 1024] sorted
    const float* weights   = (const float*)d_in[2];   // [16384, 1024]
    const void*  ray_mask  = d_in[3];                 // [16384] bool/i32/f32

    init_detect_kernel<<<1, 256>>>((const uint4*)ray_mask);
    loss_kernel<<<GRID, THREADS>>>(ray_depth, z_vals, weights, ray_mask, (float*)d_out);
}